// round 1
// baseline (speedup 1.0000x reference)
#include <cuda_runtime.h>
#include <math.h>

// Problem constants (fixed by setup_inputs)
#define TT  256
#define BB  128
#define FF  256
#define HH  512
#define G4H 2048   // 4*H
#define FQ  64     // F/4
#define HQ  128    // H/4

// ---------------- scratch (device globals; no allocations allowed) ----------
__device__ float g_Kx [FF * G4H];                         // (f, g*H+h)      2 MB
__device__ float g_KuT[G4H * HH];                         // (g*H+h, k_in)   4 MB
__device__ float g_pre[(size_t)TT * BB * G4H];            // (t*B+b, g*H+h)  268 MB
__device__ float g_hs [(size_t)(TT + 1) * BB * HH];       // slot t+1 = h_t  67 MB
__device__ float g_c  [BB * HH];

// Hamilton structure: K[input block p][output block q] = sign*comp
__constant__ int   c_comp[16] = {0,1,2,3,  1,0,3,2,  2,3,0,1,  3,2,1,0};
__constant__ float c_sign[16] = {1,1,1,1, -1,1,1,-1, -1,-1,1,1, -1,1,-1,1};

// ---------------- build Hamilton kernels ------------------------------------
__global__ void build_kernels(const float* __restrict__ Wx,
                              const float* __restrict__ Uh) {
    int idx = blockIdx.x * blockDim.x + threadIdx.x;
    if (idx < 4 * FF * HH) {
        int g = idx / (FF * HH);
        int r = idx - g * (FF * HH);
        int f = r / HH, h = r % HH;
        int p = f / FQ, fi = f % FQ;
        int q = h / HQ, hi = h % HQ;
        int c = c_comp[p * 4 + q];
        g_Kx[(size_t)f * G4H + g * HH + h] =
            c_sign[p * 4 + q] * Wx[((g * 4 + c) * FQ + fi) * HQ + hi];
    }
    if (idx < 4 * HH * HH) {
        int g = idx / (HH * HH);
        int r = idx - g * (HH * HH);
        int kin = r / HH, h = r % HH;
        int p = kin / HQ, ki = kin % HQ;
        int q = h / HQ, hi = h % HQ;
        int c = c_comp[p * 4 + q];
        // transposed: row = output col (g,h), inner = k (contiguous for float4 stream)
        g_KuT[(size_t)(g * HH + h) * HH + kin] =
            c_sign[p * 4 + q] * Uh[((g * 4 + c) * HQ + ki) * HQ + hi];
    }
}

__global__ void init_state() {
    int idx = blockIdx.x * blockDim.x + threadIdx.x;
    if (idx < BB * HH) { g_hs[idx] = 0.0f; g_c[idx] = 0.0f; }
}

// ---------------- pre = x @ Kx + bx  (32768 x 2048 x 256) -------------------
__global__ void __launch_bounds__(256) pre_gemm(const float* __restrict__ x,
                                                const float* __restrict__ bx) {
    __shared__ __align__(16) float As[16][65];
    __shared__ __align__(16) float Bs[16][64];
    const int K = FF, N = G4H;
    int m0 = blockIdx.y * 64, n0 = blockIdx.x * 64;
    int tid = threadIdx.x;
    int tx = tid & 15, ty = tid >> 4;
    int lm = tid >> 2, lk4 = (tid & 3) * 4;      // A loader: row lm, k offset lk4
    int lk = tid >> 4, ln4 = (tid & 15) * 4;     // B loader: k row lk, n offset ln4

    float acc[4][4];
#pragma unroll
    for (int i = 0; i < 4; i++)
#pragma unroll
        for (int j = 0; j < 4; j++) acc[i][j] = 0.0f;

    for (int k0 = 0; k0 < K; k0 += 16) {
        float4 av = *(const float4*)(x + (size_t)(m0 + lm) * K + k0 + lk4);
        As[lk4 + 0][lm] = av.x; As[lk4 + 1][lm] = av.y;
        As[lk4 + 2][lm] = av.z; As[lk4 + 3][lm] = av.w;
        float4 bv = *(const float4*)(g_Kx + (size_t)(k0 + lk) * N + n0 + ln4);
        *(float4*)(&Bs[lk][ln4]) = bv;
        __syncthreads();
#pragma unroll
        for (int kk = 0; kk < 16; kk++) {
            float a[4], b[4];
#pragma unroll
            for (int i = 0; i < 4; i++) a[i] = As[kk][ty + i * 16];
#pragma unroll
            for (int j = 0; j < 4; j++) b[j] = Bs[kk][tx + j * 16];
#pragma unroll
            for (int i = 0; i < 4; i++)
#pragma unroll
                for (int j = 0; j < 4; j++) acc[i][j] += a[i] * b[j];
        }
        __syncthreads();
    }
#pragma unroll
    for (int i = 0; i < 4; i++) {
        int m = m0 + ty + i * 16;
#pragma unroll
        for (int j = 0; j < 4; j++) {
            int n = n0 + tx + j * 16;
            g_pre[(size_t)m * N + n] = acc[i][j] + bx[n];
        }
    }
}

// ---------------- one recurrent step (fused GEMM + gates) -------------------
// grid = 128 blocks, each owns h in [4*bid, 4*bid+4) x all 4 gates x all 128 b.
// Ku streamed from L2 (read exactly once per step chip-wide); h tile in shared.
__global__ void __launch_bounds__(256) qlstm_step(int t) {
    __shared__ __align__(16) float sh[32][128];     // [k][b] chunk of h_{t-1}
    __shared__ float hu_sh[16 * 128];               // [(g*4+hh)][b]

    const float* __restrict__ hprev = g_hs + (size_t)t * (BB * HH);
    const float* __restrict__ pre_t = g_pre + (size_t)t * (BB * G4H);
    float* __restrict__ hout = g_hs + (size_t)(t + 1) * (BB * HH);

    int tid  = threadIdx.x;
    int lane = tid & 31;
    int slot = tid >> 5;                 // 0..7 -> 2 local cols each
    int h0   = blockIdx.x * 4;

    int lc0 = slot * 2, lc1 = slot * 2 + 1;          // local col = g*4+hh
    int g0 = lc0 >> 2, hh0 = lc0 & 3;
    int g1 = lc1 >> 2, hh1 = lc1 & 3;
    const float* __restrict__ ku0 = g_KuT + (size_t)(g0 * HH + h0 + hh0) * HH;
    const float* __restrict__ ku1 = g_KuT + (size_t)(g1 * HH + h0 + hh1) * HH;

    float acc0[4] = {0, 0, 0, 0};
    float acc1[4] = {0, 0, 0, 0};

    int jslot = tid & 7;     // k-quad within 32-chunk
    int brow  = tid >> 3;    // 0..31

    for (int kc = 0; kc < HH; kc += 32) {
        __syncthreads();
#pragma unroll
        for (int i = 0; i < 4; i++) {
            int b = brow + i * 32;
            float4 v = *(const float4*)(hprev + (size_t)b * HH + kc + jslot * 4);
            sh[jslot * 4 + 0][b] = v.x; sh[jslot * 4 + 1][b] = v.y;
            sh[jslot * 4 + 2][b] = v.z; sh[jslot * 4 + 3][b] = v.w;
        }
        __syncthreads();
#pragma unroll
        for (int k4 = 0; k4 < 32; k4 += 4) {
            float4 u0 = *(const float4*)(ku0 + kc + k4);
            float4 u1 = *(const float4*)(ku1 + kc + k4);
#pragma unroll
            for (int kk = 0; kk < 4; kk++) {
                float uu0 = ((const float*)&u0)[kk];
                float uu1 = ((const float*)&u1)[kk];
#pragma unroll
                for (int i = 0; i < 4; i++) {
                    float a = sh[k4 + kk][lane + i * 32];
                    acc0[i] += a * uu0;
                    acc1[i] += a * uu1;
                }
            }
        }
    }
#pragma unroll
    for (int i = 0; i < 4; i++) {
        hu_sh[lc0 * 128 + lane + i * 32] = acc0[i];
        hu_sh[lc1 * 128 + lane + i * 32] = acc1[i];
    }
    __syncthreads();

    // gates: one thread per batch row, all 4 h columns via float4
    if (tid < 128) {
        int b = tid;
        float4 pf4 = *(const float4*)(pre_t + (size_t)b * G4H + 0 * HH + h0);
        float4 pi4 = *(const float4*)(pre_t + (size_t)b * G4H + 1 * HH + h0);
        float4 po4 = *(const float4*)(pre_t + (size_t)b * G4H + 2 * HH + h0);
        float4 pa4 = *(const float4*)(pre_t + (size_t)b * G4H + 3 * HH + h0);
        float4 cp  = *(const float4*)(g_c + (size_t)b * HH + h0);

        float pf[4] = {pf4.x, pf4.y, pf4.z, pf4.w};
        float pi[4] = {pi4.x, pi4.y, pi4.z, pi4.w};
        float po[4] = {po4.x, po4.y, po4.z, po4.w};
        float pa[4] = {pa4.x, pa4.y, pa4.z, pa4.w};
        float cv[4] = {cp.x, cp.y, cp.z, cp.w};
        float hv[4];
#pragma unroll
        for (int hh = 0; hh < 4; hh++) {
            float f = pf[hh] + hu_sh[(0 * 4 + hh) * 128 + b];
            float i = pi[hh] + hu_sh[(1 * 4 + hh) * 128 + b];
            float o = po[hh] + hu_sh[(2 * 4 + hh) * 128 + b];
            float a = pa[hh] + hu_sh[(3 * 4 + hh) * 128 + b];
            float ft = 1.0f / (1.0f + expf(-f));
            float it = 1.0f / (1.0f + expf(-i));
            float ot = 1.0f / (1.0f + expf(-o));
            float c  = it * tanhf(a) + ft * cv[hh];
            cv[hh] = c;
            hv[hh] = ot * tanhf(c);
        }
        *(float4*)(g_c + (size_t)b * HH + h0)  = make_float4(cv[0], cv[1], cv[2], cv[3]);
        *(float4*)(hout + (size_t)b * HH + h0) = make_float4(hv[0], hv[1], hv[2], hv[3]);
    }
}

// ---------------- out = hs @ fco_w^T + fco_b  (32768 x 256 x 512) -----------
__global__ void __launch_bounds__(256) out_gemm(const float* __restrict__ w,
                                                const float* __restrict__ bias,
                                                float* __restrict__ out) {
    __shared__ __align__(16) float As[16][65];
    __shared__ __align__(16) float Bs[16][65];
    const float* __restrict__ hs = g_hs + BB * HH;   // slots 1..T contiguous
    const int K = HH, N = FF;
    int m0 = blockIdx.y * 64, n0 = blockIdx.x * 64;
    int tid = threadIdx.x;
    int tx = tid & 15, ty = tid >> 4;
    int lr = tid >> 2, lk4 = (tid & 3) * 4;

    float acc[4][4];
#pragma unroll
    for (int i = 0; i < 4; i++)
#pragma unroll
        for (int j = 0; j < 4; j++) acc[i][j] = 0.0f;

    for (int k0 = 0; k0 < K; k0 += 16) {
        float4 av = *(const float4*)(hs + (size_t)(m0 + lr) * K + k0 + lk4);
        As[lk4 + 0][lr] = av.x; As[lk4 + 1][lr] = av.y;
        As[lk4 + 2][lr] = av.z; As[lk4 + 3][lr] = av.w;
        float4 bv = *(const float4*)(w + (size_t)(n0 + lr) * K + k0 + lk4);
        Bs[lk4 + 0][lr] = bv.x; Bs[lk4 + 1][lr] = bv.y;
        Bs[lk4 + 2][lr] = bv.z; Bs[lk4 + 3][lr] = bv.w;
        __syncthreads();
#pragma unroll
        for (int kk = 0; kk < 16; kk++) {
            float a[4], b[4];
#pragma unroll
            for (int i = 0; i < 4; i++) a[i] = As[kk][ty + i * 16];
#pragma unroll
            for (int j = 0; j < 4; j++) b[j] = Bs[kk][tx + j * 16];
#pragma unroll
            for (int i = 0; i < 4; i++)
#pragma unroll
                for (int j = 0; j < 4; j++) acc[i][j] += a[i] * b[j];
        }
        __syncthreads();
    }
#pragma unroll
    for (int i = 0; i < 4; i++) {
        int m = m0 + ty + i * 16;
#pragma unroll
        for (int j = 0; j < 4; j++) {
            int n = n0 + tx + j * 16;
            out[(size_t)m * N + n] = acc[i][j] + bias[n];
        }
    }
}

// ---------------- launch -----------------------------------------------------
extern "C" void kernel_launch(void* const* d_in, const int* in_sizes, int n_in,
                              void* d_out, int out_size) {
    const float* x     = (const float*)d_in[0];
    const float* Wx    = (const float*)d_in[1];
    const float* bx    = (const float*)d_in[2];
    const float* Uh    = (const float*)d_in[3];
    const float* fco_w = (const float*)d_in[4];
    const float* fco_b = (const float*)d_in[5];
    float* out = (float*)d_out;

    build_kernels<<<4096, 256>>>(Wx, Uh);
    init_state<<<256, 256>>>();
    pre_gemm<<<dim3(G4H / 64, (TT * BB) / 64), 256>>>(x, bx);
    for (int t = 0; t < TT; t++)
        qlstm_step<<<128, 256>>>(t);
    out_gemm<<<dim3(FF / 64, (TT * BB) / 64), 256>>>(fco_w, fco_b, out);
}

// round 3
// speedup vs baseline: 1.2621x; 1.2621x over previous
#include <cuda_runtime.h>
#include <math.h>

// Problem constants (fixed by setup_inputs)
#define TT  256
#define BB  128
#define FF  256
#define HH  512
#define G4H 2048   // 4*H
#define FQ  64     // F/4
#define HQ  128    // H/4
#define NBLK 128   // persistent grid size (<=148 SMs, 1 block/SM guaranteed)

// ---------------- scratch (device globals; no allocations allowed) ----------
__device__ float g_Kx  [FF * G4H];                       // (f, g*H+h)       2 MB
__device__ float g_KuT2[HH * G4H];                       // (k_in, g*H+h)    4 MB
__device__ float g_pre [(size_t)TT * BB * G4H];          // (t*B+b, g*H+h) 268 MB
__device__ float g_hs  [(size_t)TT * BB * HH];           // h_t, batch-major 67 MB
__device__ float g_hT  [2][HH][BB];                      // ping-pong h, k-major
__device__ unsigned g_bar[TT];                           // per-step arrival counters

// Hamilton structure: K[input block p][output block q] = sign*comp
__constant__ int   c_comp[16] = {0,1,2,3,  1,0,3,2,  2,3,0,1,  3,2,1,0};
__constant__ float c_sign[16] = {1,1,1,1, -1,1,1,-1, -1,-1,1,1, -1,1,-1,1};

// ---------------- build Hamilton kernels ------------------------------------
__global__ void build_kernels(const float* __restrict__ Wx,
                              const float* __restrict__ Uh) {
    int idx = blockIdx.x * blockDim.x + threadIdx.x;
    if (idx < 4 * FF * HH) {
        int g = idx / (FF * HH);
        int r = idx - g * (FF * HH);
        int f = r / HH, h = r % HH;
        int p = f / FQ, fi = f % FQ;
        int q = h / HQ, hi = h % HQ;
        int c = c_comp[p * 4 + q];
        g_Kx[(size_t)f * G4H + g * HH + h] =
            c_sign[p * 4 + q] * Wx[((g * 4 + c) * FQ + fi) * HQ + hi];
    }
    if (idx < 4 * HH * HH) {
        int g = idx / (HH * HH);
        int r = idx - g * (HH * HH);
        int kin = r / HH, h = r % HH;
        int p = kin / HQ, ki = kin % HQ;
        int q = h / HQ, hi = h % HQ;
        int c = c_comp[p * 4 + q];
        // layout (k_in, g*H+h): inner loop reads a float4 of 4 consecutive h
        g_KuT2[(size_t)kin * G4H + g * HH + h] =
            c_sign[p * 4 + q] * Uh[((g * 4 + c) * HQ + ki) * HQ + hi];
    }
}

__global__ void init_persist() {
    int idx = blockIdx.x * blockDim.x + threadIdx.x;
    if (idx < 2 * HH * BB) ((float*)g_hT)[idx] = 0.0f;
    if (idx < TT) g_bar[idx] = 0u;
}

// ---------------- pre = x @ Kx + bx  (32768 x 2048 x 256) -------------------
__global__ void __launch_bounds__(256) pre_gemm(const float* __restrict__ x,
                                                const float* __restrict__ bx) {
    __shared__ __align__(16) float As[16][65];
    __shared__ __align__(16) float Bs[16][64];
    const int K = FF, N = G4H;
    int m0 = blockIdx.y * 64, n0 = blockIdx.x * 64;
    int tid = threadIdx.x;
    int tx = tid & 15, ty = tid >> 4;
    int lm = tid >> 2, lk4 = (tid & 3) * 4;
    int lk = tid >> 4, ln4 = (tid & 15) * 4;

    float acc[4][4];
#pragma unroll
    for (int i = 0; i < 4; i++)
#pragma unroll
        for (int j = 0; j < 4; j++) acc[i][j] = 0.0f;

    for (int k0 = 0; k0 < K; k0 += 16) {
        float4 av = *(const float4*)(x + (size_t)(m0 + lm) * K + k0 + lk4);
        As[lk4 + 0][lm] = av.x; As[lk4 + 1][lm] = av.y;
        As[lk4 + 2][lm] = av.z; As[lk4 + 3][lm] = av.w;
        float4 bv = *(const float4*)(g_Kx + (size_t)(k0 + lk) * N + n0 + ln4);
        *(float4*)(&Bs[lk][ln4]) = bv;
        __syncthreads();
#pragma unroll
        for (int kk = 0; kk < 16; kk++) {
            float a[4], b[4];
#pragma unroll
            for (int i = 0; i < 4; i++) a[i] = As[kk][ty + i * 16];
#pragma unroll
            for (int j = 0; j < 4; j++) b[j] = Bs[kk][tx + j * 16];
#pragma unroll
            for (int i = 0; i < 4; i++)
#pragma unroll
                for (int j = 0; j < 4; j++) acc[i][j] += a[i] * b[j];
        }
        __syncthreads();
    }
#pragma unroll
    for (int i = 0; i < 4; i++) {
        int m = m0 + ty + i * 16;
#pragma unroll
        for (int j = 0; j < 4; j++) {
            int n = n0 + tx + j * 16;
            g_pre[(size_t)m * N + n] = acc[i][j] + bx[n];
        }
    }
}

// ---------------- persistent recurrence kernel -------------------------------
// grid = 128 blocks x 512 threads, all co-resident (1 block/SM, 148 SMs).
// Block bid owns h-cols [4*bid, 4*bid+4) x 4 gates. Thread (cg = tid>>7,
// bp = tid&127) accumulates gate cg, all 4 h-cols, batch bp.
// Grid-wide sync per step via g_bar[t] with nanosleep backoff.
__global__ void __launch_bounds__(512, 1) qlstm_persist() {
    __shared__ __align__(16) float sh[2][32][128];   // [buf][k][b] chunk of h  32KB
    __shared__ float hu_sh[16 * 128];                // [(cg*4+hh)][b]           8KB

    const int tid = threadIdx.x;
    const int bid = blockIdx.x;
    const int cg  = tid >> 7;      // gate 0..3
    const int bp  = tid & 127;     // batch 0..127
    const int h0  = bid * 4;

    // Ku column pointer: g_KuT2[k][cg*HH + h0 .. +4)  (warp-uniform, L1-hot)
    const float* __restrict__ Kcol = g_KuT2 + (size_t)cg * HH + h0;

    // cell state lives in registers of gate threads (tid < 128)
    float cv0 = 0.f, cv1 = 0.f, cv2 = 0.f, cv3 = 0.f;

    for (int t = 0; t < TT; t++) {
        const float* __restrict__ hTr = &g_hT[t & 1][0][0];            // [512][128]
        const float* __restrict__ pre_t = g_pre + (size_t)t * BB * G4H;

        // prefetch this thread's gate preactivations (land during GEMM)
        float4 pf, pi, po, pa;
        if (tid < 128) {
            const float* p = pre_t + (size_t)tid * G4H + h0;
            pf = __ldcg((const float4*)(p + 0 * HH));
            pi = __ldcg((const float4*)(p + 1 * HH));
            po = __ldcg((const float4*)(p + 2 * HH));
            pa = __ldcg((const float4*)(p + 3 * HH));
        }

        float a0 = 0.f, a1 = 0.f, a2 = 0.f, a3 = 0.f;

        // stage chunk 0 (k = 0..31) into buffer 0  — h read via L2 (__ldcg:
        // ping-pong buffer is written by other SMs; L1 is not coherent)
#pragma unroll
        for (int i = 0; i < 2; i++) {
            int q = tid + i * 512;            // 0..1023 float4 slots
            int k = q >> 5, c4 = q & 31;
            float4 v = __ldcg((const float4*)(hTr + k * 128 + c4 * 4));
            *(float4*)&sh[0][k][c4 * 4] = v;
        }
        __syncthreads();

        int buf = 0;
        for (int kc = 0; kc < 16; kc++) {
            if (kc < 15) {
#pragma unroll
                for (int i = 0; i < 2; i++) {
                    int q = tid + i * 512;
                    int k = q >> 5, c4 = q & 31;
                    float4 v = __ldcg((const float4*)(hTr + (kc * 32 + 32 + k) * 128 + c4 * 4));
                    *(float4*)&sh[buf ^ 1][k][c4 * 4] = v;
                }
            }
            const float* __restrict__ Kp = Kcol + (size_t)(kc * 32) * G4H;
#pragma unroll
            for (int kk = 0; kk < 32; kk++) {
                float4 u = *(const float4*)(Kp + (size_t)kk * G4H);  // broadcast
                float a = sh[buf][kk][bp];
                a0 += u.x * a; a1 += u.y * a; a2 += u.z * a; a3 += u.w * a;
            }
            __syncthreads();
            buf ^= 1;
        }

        hu_sh[(cg * 4 + 0) * 128 + bp] = a0;
        hu_sh[(cg * 4 + 1) * 128 + bp] = a1;
        hu_sh[(cg * 4 + 2) * 128 + bp] = a2;
        hu_sh[(cg * 4 + 3) * 128 + bp] = a3;
        __syncthreads();

        if (tid < 128) {
            const int b = tid;
            float prf[4] = {pf.x, pf.y, pf.z, pf.w};
            float pri[4] = {pi.x, pi.y, pi.z, pi.w};
            float pro[4] = {po.x, po.y, po.z, po.w};
            float pra[4] = {pa.x, pa.y, pa.z, pa.w};
            float cvv[4] = {cv0, cv1, cv2, cv3};
            float hv[4];
#pragma unroll
            for (int hh = 0; hh < 4; hh++) {
                float f = prf[hh] + hu_sh[(0 * 4 + hh) * 128 + b];
                float i = pri[hh] + hu_sh[(1 * 4 + hh) * 128 + b];
                float o = pro[hh] + hu_sh[(2 * 4 + hh) * 128 + b];
                float a = pra[hh] + hu_sh[(3 * 4 + hh) * 128 + b];
                float ft = 1.0f / (1.0f + expf(-f));
                float it = 1.0f / (1.0f + expf(-i));
                float ot = 1.0f / (1.0f + expf(-o));
                float c  = it * tanhf(a) + ft * cvv[hh];
                cvv[hh] = c;
                hv[hh] = ot * tanhf(c);
            }
            cv0 = cvv[0]; cv1 = cvv[1]; cv2 = cvv[2]; cv3 = cvv[3];
            // batch-major history for the output GEMM
            *(float4*)(g_hs + ((size_t)t * BB + b) * HH + h0) =
                make_float4(hv[0], hv[1], hv[2], hv[3]);
            // k-major ping-pong for next step's staging (coalesced per col)
            float* hw = &g_hT[(t + 1) & 1][h0][0];
#pragma unroll
            for (int hh = 0; hh < 4; hh++) hw[hh * 128 + b] = hv[hh];
        }

        // grid-wide barrier: all h_t visible before any block starts step t+1.
        // nanosleep backoff keeps 128 spinning SMs from hammering one L2 line.
        __threadfence();
        __syncthreads();
        if (tid == 0) {
            unsigned done = atomicAdd(&g_bar[t], 1u) + 1u;
            while (done < (unsigned)NBLK) {
                __nanosleep(64);
                done = *(volatile unsigned*)&g_bar[t];
            }
        }
        __syncthreads();
    }
}

// ---------------- out = hs @ fco_w^T + fco_b  (32768 x 256 x 512) -----------
__global__ void __launch_bounds__(256) out_gemm(const float* __restrict__ w,
                                                const float* __restrict__ bias,
                                                float* __restrict__ out) {
    __shared__ __align__(16) float As[16][65];
    __shared__ __align__(16) float Bs[16][65];
    const float* __restrict__ hs = g_hs;
    const int K = HH, N = FF;
    int m0 = blockIdx.y * 64, n0 = blockIdx.x * 64;
    int tid = threadIdx.x;
    int tx = tid & 15, ty = tid >> 4;
    int lr = tid >> 2, lk4 = (tid & 3) * 4;

    float acc[4][4];
#pragma unroll
    for (int i = 0; i < 4; i++)
#pragma unroll
        for (int j = 0; j < 4; j++) acc[i][j] = 0.0f;

    for (int k0 = 0; k0 < K; k0 += 16) {
        float4 av = *(const float4*)(hs + (size_t)(m0 + lr) * K + k0 + lk4);
        As[lk4 + 0][lr] = av.x; As[lk4 + 1][lr] = av.y;
        As[lk4 + 2][lr] = av.z; As[lk4 + 3][lr] = av.w;
        float4 bv = *(const float4*)(w + (size_t)(n0 + lr) * K + k0 + lk4);
        Bs[lk4 + 0][lr] = bv.x; Bs[lk4 + 1][lr] = bv.y;
        Bs[lk4 + 2][lr] = bv.z; Bs[lk4 + 3][lr] = bv.w;
        __syncthreads();
#pragma unroll
        for (int kk = 0; kk < 16; kk++) {
            float a[4], b[4];
#pragma unroll
            for (int i = 0; i < 4; i++) a[i] = As[kk][ty + i * 16];
#pragma unroll
            for (int j = 0; j < 4; j++) b[j] = Bs[kk][tx + j * 16];
#pragma unroll
            for (int i = 0; i < 4; i++)
#pragma unroll
                for (int j = 0; j < 4; j++) acc[i][j] += a[i] * b[j];
        }
        __syncthreads();
    }
#pragma unroll
    for (int i = 0; i < 4; i++) {
        int m = m0 + ty + i * 16;
#pragma unroll
        for (int j = 0; j < 4; j++) {
            int n = n0 + tx + j * 16;
            out[(size_t)m * N + n] = acc[i][j] + bias[n];
        }
    }
}

// ---------------- launch -----------------------------------------------------
extern "C" void kernel_launch(void* const* d_in, const int* in_sizes, int n_in,
                              void* d_out, int out_size) {
    const float* x     = (const float*)d_in[0];
    const float* Wx    = (const float*)d_in[1];
    const float* bx    = (const float*)d_in[2];
    const float* Uh    = (const float*)d_in[3];
    const float* fco_w = (const float*)d_in[4];
    const float* fco_b = (const float*)d_in[5];
    float* out = (float*)d_out;

    build_kernels<<<4096, 256>>>(Wx, Uh);
    init_persist<<<512, 256>>>();
    pre_gemm<<<dim3(G4H / 64, (TT * BB) / 64), 256>>>(x, bx);
    qlstm_persist<<<NBLK, 512>>>();
    out_gemm<<<dim3(FF / 64, (TT * BB) / 64), 256>>>(fco_w, fco_b, out);
}

// round 6
// speedup vs baseline: 2.3962x; 1.8986x over previous
#include <cuda_runtime.h>
#include <cuda_bf16.h>
#include <math.h>
#include <stdint.h>

#define TT 256
#define BB 128
#define FF 256
#define HH 512
#define G4H 2048
#define FQ 64
#define HQ 128
#define NR 64          // recurrent blocks, 32 cols (8 h) each

__device__ float g_Kx [FF * G4H];
__device__ float g_pre[(size_t)TT * BB * G4H];
__device__ float g_hs [(size_t)TT * BB * HH];
__device__ __nv_bfloat16 g_KuHi[G4H * HH];   // [col=h*4+g][k]
__device__ __nv_bfloat16 g_KuLo[G4H * HH];
__device__ __nv_bfloat16 g_hHi[2][BB * HH];  // ping-pong h (row=b, 512 k)
__device__ __nv_bfloat16 g_hLo[2][BB * HH];
__device__ unsigned g_bar[TT];

__constant__ int   c_comp[16] = {0,1,2,3, 1,0,3,2, 2,3,0,1, 3,2,1,0};
__constant__ float c_sign[16] = {1,1,1,1, -1,1,1,-1, -1,-1,1,1, -1,1,-1,1};

__device__ __forceinline__ uint32_t smem_u32(const void* p) {
    uint32_t a;
    asm("{ .reg .u64 t; cvta.to.shared.u64 t, %1; cvt.u32.u64 %0, t; }" : "=r"(a) : "l"(p));
    return a;
}
#define LDSM4(r0, r1, r2, r3, a) \
    asm volatile("ldmatrix.sync.aligned.m8n8.x4.shared.b16 {%0,%1,%2,%3}, [%4];" \
                 : "=r"(r0), "=r"(r1), "=r"(r2), "=r"(r3) : "r"(a))
#define MMA16816(c, a, b) \
    asm volatile("mma.sync.aligned.m16n8k16.row.col.f32.bf16.bf16.f32 " \
                 "{%0,%1,%2,%3}, {%4,%5,%6,%7}, {%8,%9}, {%0,%1,%2,%3};" \
                 : "+f"((c)[0]), "+f"((c)[1]), "+f"((c)[2]), "+f"((c)[3]) \
                 : "r"((a)[0]), "r"((a)[1]), "r"((a)[2]), "r"((a)[3]), \
                   "r"((b)[0]), "r"((b)[1]))

// ---------------- build Hamilton kernels -------------------------------------
__global__ void build_kernels(const float* __restrict__ Wx, const float* __restrict__ Uh) {
    int idx = blockIdx.x * blockDim.x + threadIdx.x;
    if (idx < 4 * FF * HH) {
        int g = idx / (FF * HH), r = idx - g * (FF * HH);
        int f = r / HH, h = r % HH;
        int p = f / FQ, fi = f % FQ, q = h / HQ, hi = h % HQ;
        int c = c_comp[p * 4 + q];
        g_Kx[(size_t)f * G4H + g * HH + h] =
            c_sign[p * 4 + q] * Wx[((g * 4 + c) * FQ + fi) * HQ + hi];
    }
    if (idx < G4H * HH) {
        int col = idx / HH, k = idx % HH;
        int h = col >> 2, g = col & 3;
        int p = k / HQ, ki = k % HQ, q = h / HQ, hi2 = h % HQ;
        int c = c_comp[p * 4 + q];
        float v = c_sign[p * 4 + q] * Uh[((g * 4 + c) * HQ + ki) * HQ + hi2];
        __nv_bfloat16 vh = __float2bfloat16(v);
        g_KuHi[(size_t)col * HH + k] = vh;
        g_KuLo[(size_t)col * HH + k] = __float2bfloat16(v - __bfloat162float(vh));
    }
}

__global__ void init_persist() {
    int idx = blockIdx.x * blockDim.x + threadIdx.x;
    if (idx < 65536) { ((uint32_t*)g_hHi)[idx] = 0u; ((uint32_t*)g_hLo)[idx] = 0u; }
    if (idx < TT) g_bar[idx] = 0u;
}

// ---------------- pre = x @ Kx + bx ------------------------------------------
__global__ void __launch_bounds__(256) pre_gemm(const float* __restrict__ x,
                                                const float* __restrict__ bx) {
    __shared__ __align__(16) float As[16][65], Bs[16][64];
    const int K = FF, N = G4H;
    int m0 = blockIdx.y * 64, n0 = blockIdx.x * 64, tid = threadIdx.x;
    int tx = tid & 15, ty = tid >> 4, lm = tid >> 2, lk4 = (tid & 3) * 4;
    int lk = tid >> 4, ln4 = (tid & 15) * 4;
    float acc[4][4] = {};
    for (int k0 = 0; k0 < K; k0 += 16) {
        float4 av = *(const float4*)(x + (size_t)(m0 + lm) * K + k0 + lk4);
        As[lk4][lm] = av.x; As[lk4 + 1][lm] = av.y;
        As[lk4 + 2][lm] = av.z; As[lk4 + 3][lm] = av.w;
        *(float4*)(&Bs[lk][ln4]) = *(const float4*)(g_Kx + (size_t)(k0 + lk) * N + n0 + ln4);
        __syncthreads();
#pragma unroll
        for (int kk = 0; kk < 16; kk++) {
            float a[4], b[4];
#pragma unroll
            for (int i = 0; i < 4; i++) a[i] = As[kk][ty + i * 16];
#pragma unroll
            for (int j = 0; j < 4; j++) b[j] = Bs[kk][tx + j * 16];
#pragma unroll
            for (int i = 0; i < 4; i++)
#pragma unroll
                for (int j = 0; j < 4; j++) acc[i][j] += a[i] * b[j];
        }
        __syncthreads();
    }
#pragma unroll
    for (int i = 0; i < 4; i++)
#pragma unroll
        for (int j = 0; j < 4; j++) {
            int n = n0 + tx + j * 16;
            g_pre[(size_t)(m0 + ty + i * 16) * N + n] = acc[i][j] + bx[n];
        }
}

// ---------------- persistent mma.sync recurrence ------------------------------
// 64 blocks x 256 thr. Block owns cols [32*bid, 32*bid+32) (col = h*4+g; 8 h).
// Ku hi/lo resident in SMEM. h staged per K=64 chunk with reg prefetch.
// SMEM map (dynamic): BHI 0(32K) BLO 32768(32K) AHI 65536(16K) ALO 81920(16K)
//                     HU 98304(16K)  -> 114688 B
#define SM_BHI 0
#define SM_BLO 32768
#define SM_AHI 65536
#define SM_ALO 81920
#define SM_HU  98304
#define SMEM_REC (114688 + 1024)

__global__ void __launch_bounds__(256, 1) qlstm_rec() {
    extern __shared__ char dsm[];
    char* sb = (char*)(((uintptr_t)dsm + 1023) & ~(uintptr_t)1023);
    float* hu = (float*)(sb + SM_HU);                 // [32 col][128 b]

    const int tid = threadIdx.x, wid = tid >> 5, lane = tid & 31, bid = blockIdx.x;
    const int col0 = bid * 32;                        // global col base
    const int m0 = (wid & 3) * 32;                    // warp row base
    const int n0 = (wid >> 2) * 16;                   // warp col base (local)

    // ---- stage Ku hi/lo once: [32 n][512 k], 16B unit u XOR-swizzled by n&7
    for (int i = 0; i < 8; i++) {
        int u = tid + 256 * i;                        // 2048 units per array
        int n = u >> 6, s = u & 63;
        uint32_t off = (uint32_t)n * 1024 + ((uint32_t)(s ^ (n & 7)) << 4);
        *(uint4*)(sb + SM_BHI + off) = *(const uint4*)(g_KuHi + (size_t)(col0 + n) * HH + s * 8);
        *(uint4*)(sb + SM_BLO + off) = *(const uint4*)(g_KuLo + (size_t)(col0 + n) * HH + s * 8);
    }
    __syncthreads();

    // ldmatrix base addresses (per-thread, loop-invariant parts)
    const uint32_t sbu = smem_u32(sb);
    // A: row = m0 + mt*16 + (lane&15), u = ks*2 + (lane>>4)   (chunk-local)
    const int a_row_base = m0 + (lane & 15);
    const int a_u_par = lane >> 4;
    // B: m = lane>>3: n = n0 + (m>>1)*8 + (lane&7), k8u = c*8 + ks*2 + (m&1)
    const int b_n = n0 + ((lane >> 4) << 3) + (lane & 7);
    const int b_k_par = (lane >> 3) & 1;

    // epilogue mapping: b = tid&127, hq = tid>>7 (h-quad 0/1)
    const int eb = tid & 127, hq = tid >> 7;
    float cv[4] = {};
    const size_t hvec_off = (size_t)eb * HH + bid * 8 + hq * 4;

    for (int t = 0; t < TT; t++) {
        const int par = t & 1;
        const __nv_bfloat16* __restrict__ hHi = g_hHi[par];
        const __nv_bfloat16* __restrict__ hLo = g_hLo[par];
        const float* __restrict__ pre_t = g_pre + (size_t)t * BB * G4H;

        // prefetch gate preactivations: 4 gates x 4 h (this thread's quad)
        float prf[4][4];
#pragma unroll
        for (int g = 0; g < 4; g++) {
            float4 v = __ldcg((const float4*)(pre_t + (size_t)eb * G4H + g * HH + bid * 8 + hq * 4));
            prf[g][0] = v.x; prf[g][1] = v.y; prf[g][2] = v.z; prf[g][3] = v.w;
        }

        float acc[2][2][4] = {};

        // stage chunk 0: 128 rows x 8 units (hi+lo); thread does 4 units each
#pragma unroll
        for (int i = 0; i < 4; i++) {
            int q = tid + 256 * i, row = q >> 3, u = q & 7;
            uint32_t off = (uint32_t)row * 128 + ((uint32_t)(u ^ (row & 7)) << 4);
            *(uint4*)(sb + SM_AHI + off) = __ldcg((const uint4*)(hHi + (size_t)row * HH + u * 8));
            *(uint4*)(sb + SM_ALO + off) = __ldcg((const uint4*)(hLo + (size_t)row * HH + u * 8));
        }
        __syncthreads();

        for (int c = 0; c < 8; c++) {
            uint4 vh[4], vl[4];
            if (c < 7) {
#pragma unroll
                for (int i = 0; i < 4; i++) {
                    int q = tid + 256 * i, row = q >> 3, u = q & 7;
                    size_t so = (size_t)row * HH + (c + 1) * 64 + u * 8;
                    vh[i] = __ldcg((const uint4*)(hHi + so));
                    vl[i] = __ldcg((const uint4*)(hLo + so));
                }
            }
#pragma unroll
            for (int ks = 0; ks < 4; ks++) {
                uint32_t ahi[2][4], alo[2][4], bhi[4], blo[4];
#pragma unroll
                for (int mt = 0; mt < 2; mt++) {
                    int row = a_row_base + mt * 16;
                    int u = ks * 2 + a_u_par;
                    uint32_t off = (uint32_t)row * 128 + ((uint32_t)(u ^ (row & 7)) << 4);
                    LDSM4(ahi[mt][0], ahi[mt][1], ahi[mt][2], ahi[mt][3], sbu + SM_AHI + off);
                    LDSM4(alo[mt][0], alo[mt][1], alo[mt][2], alo[mt][3], sbu + SM_ALO + off);
                }
                {
                    int k8u = c * 8 + ks * 2 + b_k_par;
                    uint32_t off = (uint32_t)b_n * 1024 + ((uint32_t)(k8u ^ (b_n & 7)) << 4);
                    LDSM4(bhi[0], bhi[1], bhi[2], bhi[3], sbu + SM_BHI + off);
                    LDSM4(blo[0], blo[1], blo[2], blo[3], sbu + SM_BLO + off);
                }
#pragma unroll
                for (int mt = 0; mt < 2; mt++)
#pragma unroll
                    for (int nt = 0; nt < 2; nt++) {
                        MMA16816(acc[mt][nt], ahi[mt], bhi + nt * 2);
                        MMA16816(acc[mt][nt], alo[mt], bhi + nt * 2);
                        MMA16816(acc[mt][nt], ahi[mt], blo + nt * 2);
                    }
            }
            __syncthreads();
            if (c < 7) {
#pragma unroll
                for (int i = 0; i < 4; i++) {
                    int q = tid + 256 * i, row = q >> 3, u = q & 7;
                    uint32_t off = (uint32_t)row * 128 + ((uint32_t)(u ^ (row & 7)) << 4);
                    *(uint4*)(sb + SM_AHI + off) = vh[i];
                    *(uint4*)(sb + SM_ALO + off) = vl[i];
                }
                __syncthreads();
            }
        }

        // dump C fragments to hu[col][b]
#pragma unroll
        for (int mt = 0; mt < 2; mt++)
#pragma unroll
            for (int nt = 0; nt < 2; nt++) {
                int row = m0 + mt * 16 + (lane >> 2);
                int col = n0 + nt * 8 + 2 * (lane & 3);
                hu[col * 128 + row]           = acc[mt][nt][0];
                hu[(col + 1) * 128 + row]     = acc[mt][nt][1];
                hu[col * 128 + row + 8]       = acc[mt][nt][2];
                hu[(col + 1) * 128 + row + 8] = acc[mt][nt][3];
            }
        __syncthreads();

        // gates: this thread owns (b=eb, h quad hq) -> 4 h
        {
            float hv[4];
#pragma unroll
            for (int j = 0; j < 4; j++) {
                int cl = (hq * 4 + j) * 4;        // local col of gate 0
                float f = prf[0][j] + hu[(cl + 0) * 128 + eb];
                float i = prf[1][j] + hu[(cl + 1) * 128 + eb];
                float o = prf[2][j] + hu[(cl + 2) * 128 + eb];
                float a = prf[3][j] + hu[(cl + 3) * 128 + eb];
                float ft = 1.0f / (1.0f + expf(-f));
                float it = 1.0f / (1.0f + expf(-i));
                float ot = 1.0f / (1.0f + expf(-o));
                float cc = it * tanhf(a) + ft * cv[j];
                cv[j] = cc;
                hv[j] = ot * tanhf(cc);
            }
            *(float4*)(g_hs + ((size_t)t * BB + eb) * HH + bid * 8 + hq * 4) =
                make_float4(hv[0], hv[1], hv[2], hv[3]);
            uint32_t hp[2], lp[2];
#pragma unroll
            for (int q = 0; q < 2; q++) {
                __nv_bfloat16 b0 = __float2bfloat16(hv[2 * q]);
                __nv_bfloat16 b1 = __float2bfloat16(hv[2 * q + 1]);
                __nv_bfloat16 l0 = __float2bfloat16(hv[2 * q] - __bfloat162float(b0));
                __nv_bfloat16 l1 = __float2bfloat16(hv[2 * q + 1] - __bfloat162float(b1));
                hp[q] = (uint32_t)__bfloat16_as_ushort(b0) | ((uint32_t)__bfloat16_as_ushort(b1) << 16);
                lp[q] = (uint32_t)__bfloat16_as_ushort(l0) | ((uint32_t)__bfloat16_as_ushort(l1) << 16);
            }
            *(uint2*)(g_hHi[par ^ 1] + hvec_off) = make_uint2(hp[0], hp[1]);
            *(uint2*)(g_hLo[par ^ 1] + hvec_off) = make_uint2(lp[0], lp[1]);
        }

        // grid-wide barrier
        __threadfence();
        __syncthreads();
        if (tid == 0) {
            unsigned done = atomicAdd(&g_bar[t], 1u) + 1u;
            while (done < (unsigned)NR) { __nanosleep(64); done = *(volatile unsigned*)&g_bar[t]; }
        }
        __syncthreads();
    }
}

// ---------------- out = hs @ fco_w^T + fco_b ----------------------------------
__global__ void __launch_bounds__(256) out_gemm(const float* __restrict__ w,
                                                const float* __restrict__ bias,
                                                float* __restrict__ out) {
    __shared__ __align__(16) float As[16][65], Bs[16][65];
    const int K = HH, N = FF;
    int m0 = blockIdx.y * 64, n0 = blockIdx.x * 64, tid = threadIdx.x;
    int tx = tid & 15, ty = tid >> 4, lr = tid >> 2, lk4 = (tid & 3) * 4;
    float acc[4][4] = {};
    for (int k0 = 0; k0 < K; k0 += 16) {
        float4 av = *(const float4*)(g_hs + (size_t)(m0 + lr) * K + k0 + lk4);
        As[lk4][lr] = av.x; As[lk4 + 1][lr] = av.y;
        As[lk4 + 2][lr] = av.z; As[lk4 + 3][lr] = av.w;
        float4 bv = *(const float4*)(w + (size_t)(n0 + lr) * K + k0 + lk4);
        Bs[lk4][lr] = bv.x; Bs[lk4 + 1][lr] = bv.y;
        Bs[lk4 + 2][lr] = bv.z; Bs[lk4 + 3][lr] = bv.w;
        __syncthreads();
#pragma unroll
        for (int kk = 0; kk < 16; kk++) {
            float a[4], bb[4];
#pragma unroll
            for (int i = 0; i < 4; i++) a[i] = As[kk][ty + i * 16];
#pragma unroll
            for (int j = 0; j < 4; j++) bb[j] = Bs[kk][tx + j * 16];
#pragma unroll
            for (int i = 0; i < 4; i++)
#pragma unroll
                for (int j = 0; j < 4; j++) acc[i][j] += a[i] * bb[j];
        }
        __syncthreads();
    }
#pragma unroll
    for (int i = 0; i < 4; i++)
#pragma unroll
        for (int j = 0; j < 4; j++) {
            int n = n0 + tx + j * 16;
            out[(size_t)(m0 + ty + i * 16) * N + n] = acc[i][j] + bias[n];
        }
}

// ---------------- launch ------------------------------------------------------
extern "C" void kernel_launch(void* const* d_in, const int* in_sizes, int n_in,
                              void* d_out, int out_size) {
    const float* x     = (const float*)d_in[0];
    const float* Wx    = (const float*)d_in[1];
    const float* bx    = (const float*)d_in[2];
    const float* Uh    = (const float*)d_in[3];
    const float* fco_w = (const float*)d_in[4];
    const float* fco_b = (const float*)d_in[5];
    float* out = (float*)d_out;

    cudaFuncSetAttribute(qlstm_rec, cudaFuncAttributeMaxDynamicSharedMemorySize, SMEM_REC);
    build_kernels<<<4096, 256>>>(Wx, Uh);
    init_persist<<<512, 256>>>();
    pre_gemm<<<dim3(G4H / 64, (TT * BB) / 64), 256>>>(x, bx);
    qlstm_rec<<<NR, 256, SMEM_REC>>>();
    out_gemm<<<dim3(FF / 64, (TT * BB) / 64), 256>>>(fco_w, fco_b, out);
}

// round 9
// speedup vs baseline: 2.8019x; 1.1693x over previous
#include <cuda_runtime.h>
#include <cuda_bf16.h>
#include <math.h>
#include <stdint.h>

#define TT 256
#define BB 128
#define FF 256
#define HH 512
#define G4H 2048
#define FQ 64
#define HQ 128
#define NR 64          // recurrent blocks, 32 cols (8 h) each
#define MTOT (TT * BB)

// ---------------- scratch (device globals) -----------------------------------
__device__ float g_Kx [FF * G4H];                            // 2 MB (fp32 pre_gemm)
__device__ float g_pre[(size_t)TT * BB * G4H];               // 268 MB
__device__ float g_hs [(size_t)TT * BB * HH];                // 67 MB (fp32 out_gemm)
__device__ __nv_bfloat16 g_KuHi[G4H * HH];                   // [col=h*4+g][k]
__device__ __nv_bfloat16 g_KuLo[G4H * HH];
__device__ __nv_bfloat16 g_hsHi[(size_t)(TT + 1) * BB * HH]; // slot t = h_{t-1}
__device__ __nv_bfloat16 g_hsLo[(size_t)(TT + 1) * BB * HH];
__device__ unsigned g_bar[TT];

__constant__ int   c_comp[16] = {0,1,2,3, 1,0,3,2, 2,3,0,1, 3,2,1,0};
__constant__ float c_sign[16] = {1,1,1,1, -1,1,1,-1, -1,-1,1,1, -1,1,-1,1};

__device__ __forceinline__ uint32_t smem_u32(const void* p) {
    uint32_t a;
    asm("{ .reg .u64 t; cvta.to.shared.u64 t, %1; cvt.u32.u64 %0, t; }" : "=r"(a) : "l"(p));
    return a;
}
#define LDSM4(r0, r1, r2, r3, a) \
    asm volatile("ldmatrix.sync.aligned.m8n8.x4.shared.b16 {%0,%1,%2,%3}, [%4];" \
                 : "=r"(r0), "=r"(r1), "=r"(r2), "=r"(r3) : "r"(a))
#define MMA16816(c, a, b) \
    asm volatile("mma.sync.aligned.m16n8k16.row.col.f32.bf16.bf16.f32 " \
                 "{%0,%1,%2,%3}, {%4,%5,%6,%7}, {%8,%9}, {%0,%1,%2,%3};" \
                 : "+f"((c)[0]), "+f"((c)[1]), "+f"((c)[2]), "+f"((c)[3]) \
                 : "r"((a)[0]), "r"((a)[1]), "r"((a)[2]), "r"((a)[3]), \
                   "r"((b)[0]), "r"((b)[1]))
#define CP16(sm, gp) asm volatile("cp.async.cg.shared.global [%0], [%1], 16;" :: "r"(sm), "l"(gp))
#define CP_COMMIT() asm volatile("cp.async.commit_group;" ::: "memory")
#define CP_WAIT0()  asm volatile("cp.async.wait_group 0;" ::: "memory")

// ---------------- build Hamilton kernels -------------------------------------
__global__ void build_kernels(const float* __restrict__ Wx, const float* __restrict__ Uh) {
    int idx = blockIdx.x * blockDim.x + threadIdx.x;
    if (idx < 4 * FF * HH) {          // Kx[f][g*H+h] fp32
        int g = idx / (FF * HH), r = idx - g * (FF * HH);
        int f = r / HH, h = r % HH;
        int p = f / FQ, fi = f % FQ, q = h / HQ, hi = h % HQ;
        int c = c_comp[p * 4 + q];
        g_Kx[(size_t)f * G4H + g * HH + h] =
            c_sign[p * 4 + q] * Wx[((g * 4 + c) * FQ + fi) * HQ + hi];
    }
    if (idx < G4H * HH) {             // Ku[col=h*4+g][k] bf16 hi/lo
        int col = idx / HH, k = idx % HH;
        int h = col >> 2, g = col & 3;
        int p = k / HQ, ki = k % HQ, q = h / HQ, hi2 = h % HQ;
        int c = c_comp[p * 4 + q];
        float v = c_sign[p * 4 + q] * Uh[((g * 4 + c) * HQ + ki) * HQ + hi2];
        __nv_bfloat16 vh = __float2bfloat16(v);
        g_KuHi[idx] = vh;
        g_KuLo[idx] = __float2bfloat16(v - __bfloat162float(vh));
    }
}

__global__ void init_persist() {
    int idx = blockIdx.x * blockDim.x + threadIdx.x;
    if (idx < BB * HH / 2) {          // zero slot 0 (h_{-1}) as u32 words
        ((uint32_t*)g_hsHi)[idx] = 0u;
        ((uint32_t*)g_hsLo)[idx] = 0u;
    }
    if (idx < TT) g_bar[idx] = 0u;
}

// ---------------- pre = x @ Kx + bx  (R6-verbatim fp32) -----------------------
__global__ void __launch_bounds__(256) pre_gemm(const float* __restrict__ x,
                                                const float* __restrict__ bx) {
    __shared__ __align__(16) float As[16][65], Bs[16][64];
    const int K = FF, N = G4H;
    int m0 = blockIdx.y * 64, n0 = blockIdx.x * 64, tid = threadIdx.x;
    int tx = tid & 15, ty = tid >> 4, lm = tid >> 2, lk4 = (tid & 3) * 4;
    int lk = tid >> 4, ln4 = (tid & 15) * 4;
    float acc[4][4] = {};
    for (int k0 = 0; k0 < K; k0 += 16) {
        float4 av = *(const float4*)(x + (size_t)(m0 + lm) * K + k0 + lk4);
        As[lk4][lm] = av.x; As[lk4 + 1][lm] = av.y;
        As[lk4 + 2][lm] = av.z; As[lk4 + 3][lm] = av.w;
        *(float4*)(&Bs[lk][ln4]) = *(const float4*)(g_Kx + (size_t)(k0 + lk) * N + n0 + ln4);
        __syncthreads();
#pragma unroll
        for (int kk = 0; kk < 16; kk++) {
            float a[4], b[4];
#pragma unroll
            for (int i = 0; i < 4; i++) a[i] = As[kk][ty + i * 16];
#pragma unroll
            for (int j = 0; j < 4; j++) b[j] = Bs[kk][tx + j * 16];
#pragma unroll
            for (int i = 0; i < 4; i++)
#pragma unroll
                for (int j = 0; j < 4; j++) acc[i][j] += a[i] * b[j];
        }
        __syncthreads();
    }
#pragma unroll
    for (int i = 0; i < 4; i++)
#pragma unroll
        for (int j = 0; j < 4; j++) {
            int n = n0 + tx + j * 16;
            g_pre[(size_t)(m0 + ty + i * 16) * N + n] = acc[i][j] + bx[n];
        }
}

// ---------------- persistent mma.sync recurrence ------------------------------
// 64 blocks x 256 thr. Block owns cols [32*bid, 32*bid+32) (col = h*4+g; 8 h).
// SMEM: BHI 0(32K) BLO 32768(32K) A @65536: 2 bufs x (16K hi + 16K lo),
//       HU 131072(16K) -> 147456
#define SM_BLO 32768
#define SM_A   65536
#define SM_HU  131072
#define SMEM_REC (147456 + 1024)

#define REC_STAGE(c, buf) do {                                                    \
    _Pragma("unroll")                                                             \
    for (int i_ = 0; i_ < 4; i_++) {                                              \
        int row_ = sr + i_ * 32;                                                  \
        uint32_t off_ = (uint32_t)row_ * 128 + ((uint32_t)(su ^ (row_ & 7)) << 4);\
        CP16(sbu + SM_A + (buf) * 32768 + off_,                                   \
             hHi + (size_t)row_ * HH + (c) * 64 + su * 8);                        \
        CP16(sbu + SM_A + (buf) * 32768 + 16384 + off_,                           \
             hLo + (size_t)row_ * HH + (c) * 64 + su * 8);                        \
    }                                                                             \
    CP_COMMIT();                                                                  \
} while (0)

__global__ void __launch_bounds__(256, 1) qlstm_rec() {
    extern __shared__ char dsm[];
    char* sb = (char*)(((uintptr_t)dsm + 1023) & ~(uintptr_t)1023);
    float* hu = (float*)(sb + SM_HU);                 // [32 col][128 b]
    const uint32_t sbu = smem_u32(sb);

    const int tid = threadIdx.x, wid = tid >> 5, lane = tid & 31, bid = blockIdx.x;
    const int col0 = bid * 32;
    const int m0 = (wid & 3) * 32;                    // warp row base
    const int n0 = (wid >> 2) * 16;                   // warp col base (local)

    // stage Ku hi/lo once: [32 n][512 k], 16B unit s, XOR-swizzle by n&7
    for (int i = 0; i < 8; i++) {
        int u = tid + 256 * i;
        int n = u >> 6, s = u & 63;
        uint32_t off = (uint32_t)n * 1024 + ((uint32_t)(s ^ (n & 7)) << 4);
        *(uint4*)(sb + off) = *(const uint4*)(g_KuHi + (size_t)(col0 + n) * HH + s * 8);
        *(uint4*)(sb + SM_BLO + off) = *(const uint4*)(g_KuLo + (size_t)(col0 + n) * HH + s * 8);
    }
    __syncthreads();

    const int a_row_b = m0 + (lane & 15), a_up = lane >> 4;
    const int b_n = n0 + ((lane >> 4) << 3) + (lane & 7), b_kp = (lane >> 3) & 1;
    const int sr = tid >> 3, su = tid & 7;

    // epilogue mapping: b = tid&127, hq = tid>>7
    const int eb = tid & 127, hq = tid >> 7;
    float cv[4] = {};
    const size_t hvec_off = (size_t)eb * HH + bid * 8 + hq * 4;

    for (int t = 0; t < TT; t++) {
        const __nv_bfloat16* __restrict__ hHi = g_hsHi + (size_t)t * BB * HH;
        const __nv_bfloat16* __restrict__ hLo = g_hsLo + (size_t)t * BB * HH;
        const float* __restrict__ pre_t = g_pre + (size_t)t * BB * G4H;

        float prf[4][4];
#pragma unroll
        for (int g = 0; g < 4; g++) {
            float4 v = __ldcg((const float4*)(pre_t + (size_t)eb * G4H + g * HH + bid * 8 + hq * 4));
            prf[g][0] = v.x; prf[g][1] = v.y; prf[g][2] = v.z; prf[g][3] = v.w;
        }

        float acc[2][2][4] = {};
        REC_STAGE(0, 0);
        for (int c = 0; c < 8; c++) {
            const int buf = c & 1;
            CP_WAIT0();
            __syncthreads();
            if (c < 7) REC_STAGE(c + 1, buf ^ 1);
#pragma unroll
            for (int ks = 0; ks < 4; ks++) {
                uint32_t ahi[2][4], alo[2][4], bhi[4], blo[4];
#pragma unroll
                for (int mt = 0; mt < 2; mt++) {
                    int row = a_row_b + mt * 16;
                    int u = ks * 2 + a_up;
                    uint32_t off = (uint32_t)row * 128 + ((uint32_t)(u ^ (row & 7)) << 4);
                    LDSM4(ahi[mt][0], ahi[mt][1], ahi[mt][2], ahi[mt][3],
                          sbu + SM_A + buf * 32768 + off);
                    LDSM4(alo[mt][0], alo[mt][1], alo[mt][2], alo[mt][3],
                          sbu + SM_A + buf * 32768 + 16384 + off);
                }
                {
                    int k8u = c * 8 + ks * 2 + b_kp;
                    uint32_t off = (uint32_t)b_n * 1024 + ((uint32_t)(k8u ^ (b_n & 7)) << 4);
                    LDSM4(bhi[0], bhi[1], bhi[2], bhi[3], sbu + off);
                    LDSM4(blo[0], blo[1], blo[2], blo[3], sbu + SM_BLO + off);
                }
#pragma unroll
                for (int mt = 0; mt < 2; mt++)
#pragma unroll
                    for (int nt = 0; nt < 2; nt++) {
                        MMA16816(acc[mt][nt], ahi[mt], bhi + nt * 2);
                        MMA16816(acc[mt][nt], alo[mt], bhi + nt * 2);
                        MMA16816(acc[mt][nt], ahi[mt], blo + nt * 2);
                    }
            }
            __syncthreads();
        }

        // dump C fragments to hu[col][b]
#pragma unroll
        for (int mt = 0; mt < 2; mt++)
#pragma unroll
            for (int nt = 0; nt < 2; nt++) {
                int row = m0 + mt * 16 + (lane >> 2);
                int col = n0 + nt * 8 + 2 * (lane & 3);
                hu[col * 128 + row]           = acc[mt][nt][0];
                hu[(col + 1) * 128 + row]     = acc[mt][nt][1];
                hu[col * 128 + row + 8]       = acc[mt][nt][2];
                hu[(col + 1) * 128 + row + 8] = acc[mt][nt][3];
            }
        __syncthreads();

        {
            float hv[4];
#pragma unroll
            for (int j = 0; j < 4; j++) {
                int cl = (hq * 4 + j) * 4;
                float f = prf[0][j] + hu[(cl + 0) * 128 + eb];
                float i = prf[1][j] + hu[(cl + 1) * 128 + eb];
                float o = prf[2][j] + hu[(cl + 2) * 128 + eb];
                float a = prf[3][j] + hu[(cl + 3) * 128 + eb];
                float ft = 1.0f / (1.0f + expf(-f));
                float it = 1.0f / (1.0f + expf(-i));
                float ot = 1.0f / (1.0f + expf(-o));
                float cc2 = it * tanhf(a) + ft * cv[j];
                cv[j] = cc2;
                hv[j] = ot * tanhf(cc2);
            }
            // fp32 history for out_gemm
            *(float4*)(g_hs + ((size_t)t * BB + eb) * HH + bid * 8 + hq * 4) =
                make_float4(hv[0], hv[1], hv[2], hv[3]);
            // bf16 hi/lo history for next step's A
            uint32_t hp[2], lp[2];
#pragma unroll
            for (int q = 0; q < 2; q++) {
                __nv_bfloat16 b0 = __float2bfloat16(hv[2 * q]);
                __nv_bfloat16 b1 = __float2bfloat16(hv[2 * q + 1]);
                __nv_bfloat16 l0 = __float2bfloat16(hv[2 * q] - __bfloat162float(b0));
                __nv_bfloat16 l1 = __float2bfloat16(hv[2 * q + 1] - __bfloat162float(b1));
                hp[q] = (uint32_t)__bfloat16_as_ushort(b0) | ((uint32_t)__bfloat16_as_ushort(b1) << 16);
                lp[q] = (uint32_t)__bfloat16_as_ushort(l0) | ((uint32_t)__bfloat16_as_ushort(l1) << 16);
            }
            *(uint2*)(g_hsHi + (size_t)(t + 1) * BB * HH + hvec_off) = make_uint2(hp[0], hp[1]);
            *(uint2*)(g_hsLo + (size_t)(t + 1) * BB * HH + hvec_off) = make_uint2(lp[0], lp[1]);
        }

        __threadfence();
        __syncthreads();
        if (tid == 0) {
            unsigned done = atomicAdd(&g_bar[t], 1u) + 1u;
            while (done < (unsigned)NR) { __nanosleep(32); done = *(volatile unsigned*)&g_bar[t]; }
        }
        __syncthreads();
    }
}

// ---------------- out = hs @ fco_w^T + fco_b  (R6-verbatim fp32) --------------
__global__ void __launch_bounds__(256) out_gemm(const float* __restrict__ w,
                                                const float* __restrict__ bias,
                                                float* __restrict__ out) {
    __shared__ __align__(16) float As[16][65], Bs[16][65];
    const int K = HH, N = FF;
    int m0 = blockIdx.y * 64, n0 = blockIdx.x * 64, tid = threadIdx.x;
    int tx = tid & 15, ty = tid >> 4, lr = tid >> 2, lk4 = (tid & 3) * 4;
    float acc[4][4] = {};
    for (int k0 = 0; k0 < K; k0 += 16) {
        float4 av = *(const float4*)(g_hs + (size_t)(m0 + lr) * K + k0 + lk4);
        As[lk4][lr] = av.x; As[lk4 + 1][lr] = av.y;
        As[lk4 + 2][lr] = av.z; As[lk4 + 3][lr] = av.w;
        float4 bv = *(const float4*)(w + (size_t)(n0 + lr) * K + k0 + lk4);
        Bs[lk4][lr] = bv.x; Bs[lk4 + 1][lr] = bv.y;
        Bs[lk4 + 2][lr] = bv.z; Bs[lk4 + 3][lr] = bv.w;
        __syncthreads();
#pragma unroll
        for (int kk = 0; kk < 16; kk++) {
            float a[4], bb[4];
#pragma unroll
            for (int i = 0; i < 4; i++) a[i] = As[kk][ty + i * 16];
#pragma unroll
            for (int j = 0; j < 4; j++) bb[j] = Bs[kk][tx + j * 16];
#pragma unroll
            for (int i = 0; i < 4; i++)
#pragma unroll
                for (int j = 0; j < 4; j++) acc[i][j] += a[i] * bb[j];
        }
        __syncthreads();
    }
#pragma unroll
    for (int i = 0; i < 4; i++)
#pragma unroll
        for (int j = 0; j < 4; j++) {
            int n = n0 + tx + j * 16;
            out[(size_t)(m0 + ty + i * 16) * N + n] = acc[i][j] + bias[n];
        }
}

// ---------------- launch ------------------------------------------------------
extern "C" void kernel_launch(void* const* d_in, const int* in_sizes, int n_in,
                              void* d_out, int out_size) {
    const float* x     = (const float*)d_in[0];
    const float* Wx    = (const float*)d_in[1];
    const float* bx    = (const float*)d_in[2];
    const float* Uh    = (const float*)d_in[3];
    const float* fco_w = (const float*)d_in[4];
    const float* fco_b = (const float*)d_in[5];
    float* out = (float*)d_out;

    cudaFuncSetAttribute(qlstm_rec, cudaFuncAttributeMaxDynamicSharedMemorySize, SMEM_REC);
    build_kernels<<<4096, 256>>>(Wx, Uh);
    init_persist<<<256, 256>>>();
    pre_gemm<<<dim3(G4H / 64, MTOT / 64), 256>>>(x, bx);
    qlstm_rec<<<NR, 256, SMEM_REC>>>();
    out_gemm<<<dim3(FF / 64, MTOT / 64), 256>>>(fco_w, fco_b, out);
}

// round 12
// speedup vs baseline: 3.5615x; 1.2711x over previous
#include <cuda_runtime.h>
#include <cuda_bf16.h>
#include <math.h>
#include <stdint.h>

#define TT 256
#define BB 128
#define FF 256
#define HH 512
#define G4H 2048
#define FQ 64
#define HQ 128
#define NR 64
#define MTOT (TT * BB)

// ---------------- scratch (device globals) -----------------------------------
__device__ float g_pre[(size_t)TT * BB * G4H];               // 268 MB
__device__ __nv_bfloat16 g_xHi[(size_t)MTOT * FF];           // 16 MB
__device__ __nv_bfloat16 g_xLo[(size_t)MTOT * FF];
__device__ __nv_bfloat16 g_KxT_Hi[G4H * FF];                 // [n=g*H+h][k=f]
__device__ __nv_bfloat16 g_KxT_Lo[G4H * FF];
__device__ __nv_bfloat16 g_KuHi[G4H * HH];                   // [col=h*4+g][k]
__device__ __nv_bfloat16 g_KuLo[G4H * HH];
__device__ __nv_bfloat16 g_fwHi[FF * HH];                    // [n=f][k=h]
__device__ __nv_bfloat16 g_fwLo[FF * HH];
__device__ __nv_bfloat16 g_hsHi[(size_t)(TT + 1) * BB * HH]; // slot t = h_{t-1}
__device__ __nv_bfloat16 g_hsLo[(size_t)(TT + 1) * BB * HH];
__device__ unsigned g_bar[TT];

__constant__ int   c_comp[16] = {0,1,2,3, 1,0,3,2, 2,3,0,1, 3,2,1,0};
__constant__ float c_sign[16] = {1,1,1,1, -1,1,1,-1, -1,-1,1,1, -1,1,-1,1};

__device__ __forceinline__ uint32_t smem_u32(const void* p) {
    uint32_t a;
    asm("{ .reg .u64 t; cvta.to.shared.u64 t, %1; cvt.u32.u64 %0, t; }" : "=r"(a) : "l"(p));
    return a;
}
#define LDSM4(r0, r1, r2, r3, a) \
    asm volatile("ldmatrix.sync.aligned.m8n8.x4.shared.b16 {%0,%1,%2,%3}, [%4];" \
                 : "=r"(r0), "=r"(r1), "=r"(r2), "=r"(r3) : "r"(a))
#define MMA16816(c, a, b) \
    asm volatile("mma.sync.aligned.m16n8k16.row.col.f32.bf16.bf16.f32 " \
                 "{%0,%1,%2,%3}, {%4,%5,%6,%7}, {%8,%9}, {%0,%1,%2,%3};" \
                 : "+f"((c)[0]), "+f"((c)[1]), "+f"((c)[2]), "+f"((c)[3]) \
                 : "r"((a)[0]), "r"((a)[1]), "r"((a)[2]), "r"((a)[3]), \
                   "r"((b)[0]), "r"((b)[1]))
#define CP16(sm, gp) asm volatile("cp.async.cg.shared.global [%0], [%1], 16;" :: "r"(sm), "l"(gp))
#define CP_COMMIT() asm volatile("cp.async.commit_group;" ::: "memory")
#define CP_WAIT0()  asm volatile("cp.async.wait_group 0;" ::: "memory")
#define CP_WAIT1()  asm volatile("cp.async.wait_group 1;" ::: "memory")

// ---------------- build Hamilton kernels + splits -----------------------------
__global__ void build_kernels(const float* __restrict__ Wx, const float* __restrict__ Uh) {
    int idx = blockIdx.x * blockDim.x + threadIdx.x;
    if (idx < G4H * FF) {             // KxT[n][k]
        int n = idx / FF, k = idx % FF;
        int g = n / HH, h = n % HH;
        int p = k / FQ, fi = k % FQ, q = h / HQ, hi = h % HQ;
        int c = c_comp[p * 4 + q];
        float v = c_sign[p * 4 + q] * Wx[((g * 4 + c) * FQ + fi) * HQ + hi];
        __nv_bfloat16 vh = __float2bfloat16(v);
        g_KxT_Hi[idx] = vh;
        g_KxT_Lo[idx] = __float2bfloat16(v - __bfloat162float(vh));
    }
    if (idx < G4H * HH) {             // Ku[col=h*4+g][k]
        int col = idx / HH, k = idx % HH;
        int h = col >> 2, g = col & 3;
        int p = k / HQ, ki = k % HQ, q = h / HQ, hi2 = h % HQ;
        int c = c_comp[p * 4 + q];
        float v = c_sign[p * 4 + q] * Uh[((g * 4 + c) * HQ + ki) * HQ + hi2];
        __nv_bfloat16 vh = __float2bfloat16(v);
        g_KuHi[idx] = vh;
        g_KuLo[idx] = __float2bfloat16(v - __bfloat162float(vh));
    }
}

__global__ void split_inputs(const float* __restrict__ x, const float* __restrict__ fw) {
    int idx = blockIdx.x * blockDim.x + threadIdx.x;
    if (idx < MTOT * FF) {
        float v = x[idx];
        __nv_bfloat16 vh = __float2bfloat16(v);
        g_xHi[idx] = vh;
        g_xLo[idx] = __float2bfloat16(v - __bfloat162float(vh));
    }
    if (idx < FF * HH) {
        float v = fw[idx];
        __nv_bfloat16 vh = __float2bfloat16(v);
        g_fwHi[idx] = vh;
        g_fwLo[idx] = __float2bfloat16(v - __bfloat162float(vh));
    }
    if (idx < BB * HH / 2) {          // zero slot 0 as u32 words
        ((uint32_t*)g_hsHi)[idx] = 0u;
        ((uint32_t*)g_hsLo)[idx] = 0u;
    }
    if (idx < TT) g_bar[idx] = 0u;
}

// ---------------- bf16x3 GEMM body: block 128m x 32n (rec-proven profile) -----
// SMEM: A 3 bufs x (16K hi + 16K lo) @0; B resident @98304 (hi, lo at +64*KTOT)
#define G_B 98304
#define GEMM_SMEM(KTOT) (G_B + 128 * (KTOT) + 1024)

#define GEMM_STAGE_A(c, buf) do {                                                 \
    _Pragma("unroll")                                                             \
    for (int i_ = 0; i_ < 4; i_++) {                                              \
        int row_ = sr + i_ * 32;                                                  \
        uint32_t off_ = (uint32_t)row_ * 128 + ((uint32_t)(su ^ (row_ & 7)) << 4);\
        CP16(sbu + (buf) * 32768 + off_,                                          \
             AHi + (size_t)(m0 + row_) * KTOT + (c) * 64 + su * 8);               \
        CP16(sbu + (buf) * 32768 + 16384 + off_,                                  \
             ALo + (size_t)(m0 + row_) * KTOT + (c) * 64 + su * 8);               \
    }                                                                             \
    CP_COMMIT();                                                                  \
} while (0)

template <int KTOT>
__device__ __forceinline__ void gemm_body(
    const __nv_bfloat16* __restrict__ AHi, const __nv_bfloat16* __restrict__ ALo,
    const __nv_bfloat16* __restrict__ BHi, const __nv_bfloat16* __restrict__ BLo,
    const float* __restrict__ bias, float* __restrict__ C, int N) {
    extern __shared__ char dsm[];
    char* sb = (char*)(((uintptr_t)dsm + 1023) & ~(uintptr_t)1023);
    const uint32_t sbu = smem_u32(sb);
    const int tid = threadIdx.x, wid = tid >> 5, lane = tid & 31;
    const int m0 = blockIdx.y * 128, n0g = blockIdx.x * 32;
    const int wm = (wid & 3) * 32, wn = (wid >> 2) * 16;
    const int sr = tid >> 3, su = tid & 7;

    // stage B resident: [32 n][KTOT k] hi/lo, swizzled
#pragma unroll
    for (int i = 0; i < KTOT / 64; i++) {
        int u = tid + 256 * i;
        int n = u / (KTOT / 8), s = u % (KTOT / 8);
        uint32_t off = (uint32_t)n * (2 * KTOT) + ((uint32_t)(s ^ (n & 7)) << 4);
        *(uint4*)(sb + G_B + off) = *(const uint4*)(BHi + (size_t)(n0g + n) * KTOT + s * 8);
        *(uint4*)(sb + G_B + 64 * KTOT + off) = *(const uint4*)(BLo + (size_t)(n0g + n) * KTOT + s * 8);
    }

    const int a_row_b = wm + (lane & 15), a_up = lane >> 4;
    const int b_n = wn + ((lane >> 4) << 3) + (lane & 7), b_kp = (lane >> 3) & 1;

    float acc[2][2][4] = {};
    GEMM_STAGE_A(0, 0);
    GEMM_STAGE_A(1, 1);
    __syncthreads();    // B resident ready (also covers A group ordering)

    const int NCH = KTOT / 64;
    for (int c = 0; c < NCH; c++) {
        const int buf = c % 3;
        if (c < NCH - 1) CP_WAIT1(); else CP_WAIT0();
        __syncthreads();
        if (c + 2 < NCH) GEMM_STAGE_A(c + 2, (c + 2) % 3);
#pragma unroll
        for (int ks = 0; ks < 4; ks++) {
            uint32_t ahi[2][4], alo[2][4], bhi[4], blo[4];
#pragma unroll
            for (int mt = 0; mt < 2; mt++) {
                int row = a_row_b + mt * 16;
                int u = ks * 2 + a_up;
                uint32_t off = (uint32_t)row * 128 + ((uint32_t)(u ^ (row & 7)) << 4);
                LDSM4(ahi[mt][0], ahi[mt][1], ahi[mt][2], ahi[mt][3], sbu + buf * 32768 + off);
                LDSM4(alo[mt][0], alo[mt][1], alo[mt][2], alo[mt][3], sbu + buf * 32768 + 16384 + off);
            }
            {
                int k8u = c * 8 + ks * 2 + b_kp;
                uint32_t off = (uint32_t)b_n * (2 * KTOT) + ((uint32_t)(k8u ^ (b_n & 7)) << 4);
                LDSM4(bhi[0], bhi[1], bhi[2], bhi[3], sbu + G_B + off);
                LDSM4(blo[0], blo[1], blo[2], blo[3], sbu + G_B + 64 * KTOT + off);
            }
#pragma unroll
            for (int mt = 0; mt < 2; mt++)
#pragma unroll
                for (int nt = 0; nt < 2; nt++) {
                    MMA16816(acc[mt][nt], ahi[mt], bhi + nt * 2);
                    MMA16816(acc[mt][nt], alo[mt], bhi + nt * 2);
                    MMA16816(acc[mt][nt], ahi[mt], blo + nt * 2);
                }
        }
    }

#pragma unroll
    for (int mt = 0; mt < 2; mt++)
#pragma unroll
        for (int nt = 0; nt < 2; nt++) {
            int r = m0 + wm + mt * 16 + (lane >> 2);
            int cc = n0g + wn + nt * 8 + 2 * (lane & 3);
            float b0 = bias[cc], b1 = bias[cc + 1];
            *(float2*)(C + (size_t)r * N + cc) =
                make_float2(acc[mt][nt][0] + b0, acc[mt][nt][1] + b1);
            *(float2*)(C + (size_t)(r + 8) * N + cc) =
                make_float2(acc[mt][nt][2] + b0, acc[mt][nt][3] + b1);
        }
}

__global__ void __launch_bounds__(256, 1) gemm_pre(const float* __restrict__ bx) {
    gemm_body<FF>(g_xHi, g_xLo, g_KxT_Hi, g_KxT_Lo, bx, g_pre, G4H);
}
__global__ void __launch_bounds__(256, 1) gemm_out(const float* __restrict__ fco_b,
                                                   float* __restrict__ out) {
    gemm_body<HH>(g_hsHi + (size_t)BB * HH, g_hsLo + (size_t)BB * HH,
                  g_fwHi, g_fwLo, fco_b, out, FF);
}

// ---------------- persistent mma.sync recurrence (R9-proven 2-stage) ----------
// 64 blocks x 256 thr. Block owns cols [32*bid, 32*bid+32) (col = h*4+g; 8 h).
// SMEM: BHI 0(32K) BLO 32768(32K) A @65536: 2 bufs x (16K hi + 16K lo),
//       HU @131072 (16K) -> 147456
#define R_BLO 32768
#define R_A   65536
#define R_HU  131072
#define SMEM_REC (147456 + 1024)

#define REC_STAGE(c, buf) do {                                                    \
    _Pragma("unroll")                                                             \
    for (int i_ = 0; i_ < 4; i_++) {                                              \
        int row_ = sr + i_ * 32;                                                  \
        uint32_t off_ = (uint32_t)row_ * 128 + ((uint32_t)(su ^ (row_ & 7)) << 4);\
        CP16(sbu + R_A + (buf) * 32768 + off_,                                    \
             hHi + (size_t)row_ * HH + (c) * 64 + su * 8);                        \
        CP16(sbu + R_A + (buf) * 32768 + 16384 + off_,                            \
             hLo + (size_t)row_ * HH + (c) * 64 + su * 8);                        \
    }                                                                             \
    CP_COMMIT();                                                                  \
} while (0)

__global__ void __launch_bounds__(256, 1) qlstm_rec() {
    extern __shared__ char dsm[];
    char* sb = (char*)(((uintptr_t)dsm + 1023) & ~(uintptr_t)1023);
    float* hu = (float*)(sb + R_HU);                  // [32 col][128 b]
    const uint32_t sbu = smem_u32(sb);

    const int tid = threadIdx.x, wid = tid >> 5, lane = tid & 31, bid = blockIdx.x;
    const int col0 = bid * 32;
    const int m0 = (wid & 3) * 32;
    const int n0 = (wid >> 2) * 16;

    // stage Ku hi/lo once
    for (int i = 0; i < 8; i++) {
        int u = tid + 256 * i;
        int n = u >> 6, s = u & 63;
        uint32_t off = (uint32_t)n * 1024 + ((uint32_t)(s ^ (n & 7)) << 4);
        *(uint4*)(sb + off) = *(const uint4*)(g_KuHi + (size_t)(col0 + n) * HH + s * 8);
        *(uint4*)(sb + R_BLO + off) = *(const uint4*)(g_KuLo + (size_t)(col0 + n) * HH + s * 8);
    }
    __syncthreads();

    const int a_row_b = m0 + (lane & 15), a_up = lane >> 4;
    const int b_n = n0 + ((lane >> 4) << 3) + (lane & 7), b_kp = (lane >> 3) & 1;
    const int sr = tid >> 3, su = tid & 7;

    const int eb = tid & 127, hq = tid >> 7;
    float cv[4] = {};
    const size_t hvec_off = (size_t)eb * HH + bid * 8 + hq * 4;

    for (int t = 0; t < TT; t++) {
        const __nv_bfloat16* __restrict__ hHi = g_hsHi + (size_t)t * BB * HH;
        const __nv_bfloat16* __restrict__ hLo = g_hsLo + (size_t)t * BB * HH;
        const float* __restrict__ pre_t = g_pre + (size_t)t * BB * G4H;

        float prf[4][4];
#pragma unroll
        for (int g = 0; g < 4; g++) {
            float4 v = __ldcg((const float4*)(pre_t + (size_t)eb * G4H + g * HH + bid * 8 + hq * 4));
            prf[g][0] = v.x; prf[g][1] = v.y; prf[g][2] = v.z; prf[g][3] = v.w;
        }

        float acc[2][2][4] = {};
        REC_STAGE(0, 0);
        for (int c = 0; c < 8; c++) {
            const int buf = c & 1;
            CP_WAIT0();
            __syncthreads();
            if (c < 7) REC_STAGE(c + 1, buf ^ 1);
#pragma unroll
            for (int ks = 0; ks < 4; ks++) {
                uint32_t ahi[2][4], alo[2][4], bhi[4], blo[4];
#pragma unroll
                for (int mt = 0; mt < 2; mt++) {
                    int row = a_row_b + mt * 16;
                    int u = ks * 2 + a_up;
                    uint32_t off = (uint32_t)row * 128 + ((uint32_t)(u ^ (row & 7)) << 4);
                    LDSM4(ahi[mt][0], ahi[mt][1], ahi[mt][2], ahi[mt][3],
                          sbu + R_A + buf * 32768 + off);
                    LDSM4(alo[mt][0], alo[mt][1], alo[mt][2], alo[mt][3],
                          sbu + R_A + buf * 32768 + 16384 + off);
                }
                {
                    int k8u = c * 8 + ks * 2 + b_kp;
                    uint32_t off = (uint32_t)b_n * 1024 + ((uint32_t)(k8u ^ (b_n & 7)) << 4);
                    LDSM4(bhi[0], bhi[1], bhi[2], bhi[3], sbu + off);
                    LDSM4(blo[0], blo[1], blo[2], blo[3], sbu + R_BLO + off);
                }
#pragma unroll
                for (int mt = 0; mt < 2; mt++)
#pragma unroll
                    for (int nt = 0; nt < 2; nt++) {
                        MMA16816(acc[mt][nt], ahi[mt], bhi + nt * 2);
                        MMA16816(acc[mt][nt], alo[mt], bhi + nt * 2);
                        MMA16816(acc[mt][nt], ahi[mt], blo + nt * 2);
                    }
            }
            __syncthreads();
        }

        // dump C fragments to hu[col][b]
#pragma unroll
        for (int mt = 0; mt < 2; mt++)
#pragma unroll
            for (int nt = 0; nt < 2; nt++) {
                int row = m0 + mt * 16 + (lane >> 2);
                int col = n0 + nt * 8 + 2 * (lane & 3);
                hu[col * 128 + row]           = acc[mt][nt][0];
                hu[(col + 1) * 128 + row]     = acc[mt][nt][1];
                hu[col * 128 + row + 8]       = acc[mt][nt][2];
                hu[(col + 1) * 128 + row + 8] = acc[mt][nt][3];
            }
        __syncthreads();

        {
            float hv[4];
#pragma unroll
            for (int j = 0; j < 4; j++) {
                int cl = (hq * 4 + j) * 4;
                float f = prf[0][j] + hu[(cl + 0) * 128 + eb];
                float i = prf[1][j] + hu[(cl + 1) * 128 + eb];
                float o = prf[2][j] + hu[(cl + 2) * 128 + eb];
                float a = prf[3][j] + hu[(cl + 3) * 128 + eb];
                float ft = 1.0f / (1.0f + expf(-f));
                float it = 1.0f / (1.0f + expf(-i));
                float ot = 1.0f / (1.0f + expf(-o));
                float cc2 = it * tanhf(a) + ft * cv[j];
                cv[j] = cc2;
                hv[j] = ot * tanhf(cc2);
            }
            uint32_t hp[2], lp[2];
#pragma unroll
            for (int q = 0; q < 2; q++) {
                __nv_bfloat16 b0 = __float2bfloat16(hv[2 * q]);
                __nv_bfloat16 b1 = __float2bfloat16(hv[2 * q + 1]);
                __nv_bfloat16 l0 = __float2bfloat16(hv[2 * q] - __bfloat162float(b0));
                __nv_bfloat16 l1 = __float2bfloat16(hv[2 * q + 1] - __bfloat162float(b1));
                hp[q] = (uint32_t)__bfloat16_as_ushort(b0) | ((uint32_t)__bfloat16_as_ushort(b1) << 16);
                lp[q] = (uint32_t)__bfloat16_as_ushort(l0) | ((uint32_t)__bfloat16_as_ushort(l1) << 16);
            }
            *(uint2*)(g_hsHi + (size_t)(t + 1) * BB * HH + hvec_off) = make_uint2(hp[0], hp[1]);
            *(uint2*)(g_hsLo + (size_t)(t + 1) * BB * HH + hvec_off) = make_uint2(lp[0], lp[1]);
        }

        __threadfence();
        __syncthreads();
        if (tid == 0) {
            unsigned done = atomicAdd(&g_bar[t], 1u) + 1u;
            while (done < (unsigned)NR) { __nanosleep(64); done = *(volatile unsigned*)&g_bar[t]; }
        }
        __syncthreads();
    }
}

// ---------------- launch ------------------------------------------------------
extern "C" void kernel_launch(void* const* d_in, const int* in_sizes, int n_in,
                              void* d_out, int out_size) {
    const float* x     = (const float*)d_in[0];
    const float* Wx    = (const float*)d_in[1];
    const float* bx    = (const float*)d_in[2];
    const float* Uh    = (const float*)d_in[3];
    const float* fco_w = (const float*)d_in[4];
    const float* fco_b = (const float*)d_in[5];
    float* out = (float*)d_out;

    cudaFuncSetAttribute(qlstm_rec, cudaFuncAttributeMaxDynamicSharedMemorySize, SMEM_REC);
    cudaFuncSetAttribute(gemm_pre, cudaFuncAttributeMaxDynamicSharedMemorySize, GEMM_SMEM(FF));
    cudaFuncSetAttribute(gemm_out, cudaFuncAttributeMaxDynamicSharedMemorySize, GEMM_SMEM(HH));

    build_kernels<<<4096, 256>>>(Wx, Uh);
    split_inputs<<<MTOT * FF / 256, 256>>>(x, fco_w);
    gemm_pre<<<dim3(G4H / 32, MTOT / 128), 256, GEMM_SMEM(FF)>>>(bx);
    qlstm_rec<<<NR, 256, SMEM_REC>>>();
    gemm_out<<<dim3(FF / 32, MTOT / 128), 256, GEMM_SMEM(HH)>>>(fco_b, out);
}